// round 13
// baseline (speedup 1.0000x reference)
#include <cuda_runtime.h>
#include <cstddef>

// Problem constants (fixed by the dataset)
#define BATCH 4
#define CH    32
#define HH    120
#define WW    160
#define NXc   160
#define NYc   160
#define NZc   64
#define NVOX  (NXc * NYc * NZc)     // 1,638,400
#define HW    (HH * WW)             // 19,200

#define GRP_PER_BLK 32              // voxel-groups (of 4 z-voxels) per block
#define CH_SPLIT    8               // warps per block, each owns 4 channels
#define CH_PER_T    (CH / CH_SPLIT) // 4

// Cooperative block: 256 threads, 32 voxel-groups x 32 channels.
//
// Phase 1: threads 0..127 each project ONE voxel (group g = t>>2, m = t&3)
//          and write its gather index + validity mask to smem. This removes
//          the redundant per-channel-slice projection recompute that sank R12
//          (issue 57%, fma/alu ~26% at CH_SPLIT=8-with-recompute): only 128
//          projections per block instead of 1024.
// Phase 2: warp h (0..7) owns channels [4h,4h+4); lane g owns voxel-group g.
//          Per thread: 4 channels x (4 predicated LDG + 1 __stcs float4) --
//          the short dependency chain that R10/R12 showed is optimal.
//          A warp's stores cover 512 consecutive floats: perfectly coalesced.
// Warp 0 additionally streams the valid mask straight from smem.
//
// Gathers stay in native [B,C,H,W] layout (R9 proved [HW][C] is worse:
// adjacent lanes in a channel plane share cache lines).
//
// Projection math uses explicit IEEE-rounded intrinsics to bit-match the XLA
// reference (verified rel_err == 0.0 in R6-R12):
//   world  = coords*vs + origin          (separate mul, add -- NO fma)
//   camera = sum_j P[i,j]*world[j]       (rounded products, ascending adds)
//   u      = camera_x / camera_z         (IEEE correctly-rounded divide)
//   px     = round-half-even(u)          (__float2int_rn == jnp.round)
__global__ __launch_bounds__(256, 8) void backproject_kernel(
    const float* __restrict__ origin,      // [B,3]
    const float* __restrict__ projection,  // [B,3,4]
    const float* __restrict__ features,    // [B,C,H,W]
    const float* __restrict__ voxel_size,  // [1]
    float* __restrict__ out)               // volume [B,C,NVOX] ++ valid [B,NVOX]
{
    __shared__ int   s_fidx[GRP_PER_BLK * 4];   // gather index per voxel
    __shared__ float s_mask[GRP_PER_BLK * 4];   // 1.0 valid / 0.0 invalid

    const int blocks_per_batch = (NVOX / 4) / GRP_PER_BLK;   // 12,800
    int bid = blockIdx.x;
    int b   = bid / blocks_per_batch;
    int r0  = (bid % blocks_per_batch) * GRP_PER_BLK;        // first group

    int t = threadIdx.x;

    // ---------------- Phase 1: 128 projections ----------------
    if (t < GRP_PER_BLK * 4) {
        int g = t >> 2;            // group within block
        int m = t & 3;             // z-offset within group
        int v = (r0 + g) * 4 + m;  // voxel index within batch
        int k  = v & (NZc - 1);
        int ij = v >> 6;
        int j  = ij % NYc;
        int i  = ij / NYc;

        const float vs = __ldg(voxel_size);
        const float* P = projection + b * 12;
        float P00 = __ldg(P + 0),  P01 = __ldg(P + 1),  P02 = __ldg(P + 2),  P03 = __ldg(P + 3);
        float P10 = __ldg(P + 4),  P11 = __ldg(P + 5),  P12 = __ldg(P + 6),  P13 = __ldg(P + 7);
        float P20 = __ldg(P + 8),  P21 = __ldg(P + 9),  P22 = __ldg(P + 10), P23 = __ldg(P + 11);
        float ox = __ldg(origin + b * 3 + 0);
        float oy = __ldg(origin + b * 3 + 1);
        float oz = __ldg(origin + b * 3 + 2);

        // world = coords*vs + origin, separately rounded (NO fma)
        float wx = __fadd_rn(__fmul_rn((float)i, vs), ox);
        float wy = __fadd_rn(__fmul_rn((float)j, vs), oy);
        float wz = __fadd_rn(__fmul_rn((float)k, vs), oz);

        // camera_i = ((P_i0*wx + P_i1*wy) + P_i2*wz) + P_i3, each op rounded
        float cx = __fadd_rn(__fadd_rn(__fadd_rn(__fmul_rn(P00, wx),
                                                  __fmul_rn(P01, wy)),
                                        __fmul_rn(P02, wz)), P03);
        float cy = __fadd_rn(__fadd_rn(__fadd_rn(__fmul_rn(P10, wx),
                                                  __fmul_rn(P11, wy)),
                                        __fmul_rn(P12, wz)), P13);
        float cz = __fadd_rn(__fadd_rn(__fadd_rn(__fmul_rn(P20, wx),
                                                  __fmul_rn(P21, wy)),
                                        __fmul_rn(P22, wz)), P23);

        float u = __fdiv_rn(cx, cz);   // IEEE rn divide
        float v2 = __fdiv_rn(cy, cz);
        int ipx = __float2int_rn(u);   // round-half-even == jnp.round
        int ipy = __float2int_rn(v2);
        bool ok = (ipx >= 0) && (ipy >= 0) && (ipx < WW) && (ipy < HH) && (cz > 0.0f);
        int cpx = min(max(ipx, 0), WW - 1);
        int cpy = min(max(ipy, 0), HH - 1);
        s_fidx[t] = cpy * WW + cpx;
        s_mask[t] = ok ? 1.0f : 0.0f;
    }
    __syncthreads();

    // ---------------- Phase 2: gather + store ----------------
    int h = t >> 5;                // warp id -> channel slice
    int g = t & 31;                // lane -> voxel group
    int c0 = h * CH_PER_T;
    int v0 = (r0 + g) * 4;

    int4   fi = *reinterpret_cast<const int4*>(s_fidx + g * 4);
    float4 mk = *reinterpret_cast<const float4*>(s_mask + g * 4);
    bool ok0 = mk.x != 0.0f, ok1 = mk.y != 0.0f, ok2 = mk.z != 0.0f, ok3 = mk.w != 0.0f;

    float* vol = out + ((size_t)b * CH + c0) * NVOX + v0;

    if (ok0 | ok1 | ok2 | ok3) {
        const float* fb = features + ((size_t)b * CH + c0) * HW;
#pragma unroll
        for (int c = 0; c < CH_PER_T; ++c) {
            const float* fc = fb + (size_t)c * HW;
            float4 o = make_float4(0.f, 0.f, 0.f, 0.f);
            if (ok0) o.x = __ldg(fc + fi.x);
            if (ok1) o.y = __ldg(fc + fi.y);
            if (ok2) o.z = __ldg(fc + fi.z);
            if (ok3) o.w = __ldg(fc + fi.w);
            __stcs(reinterpret_cast<float4*>(vol + (size_t)c * NVOX), o);
        }
    } else {
        const float4 zero = make_float4(0.f, 0.f, 0.f, 0.f);
#pragma unroll
        for (int c = 0; c < CH_PER_T; ++c)
            __stcs(reinterpret_cast<float4*>(vol + (size_t)c * NVOX), zero);
    }

    if (h == 0) {
        float* vout = out + (size_t)BATCH * CH * NVOX + (size_t)b * NVOX + v0;
        __stcs(reinterpret_cast<float4*>(vout), mk);
    }
}

extern "C" void kernel_launch(void* const* d_in, const int* in_sizes, int n_in,
                              void* d_out, int out_size)
{
    // Expected metadata order: origin[12], projection[48], features[2457600],
    // voxel_size[1]. Identify tensors by unique sizes as a guard.
    const float* origin     = (const float*)d_in[0];
    const float* projection = (const float*)d_in[1];
    const float* features   = (const float*)d_in[2];
    const float* voxel_size = (const float*)d_in[3];
    for (int t = 0; t < n_in; ++t) {
        if (in_sizes[t] == BATCH * CH * HH * WW) features   = (const float*)d_in[t];
        else if (in_sizes[t] == BATCH * 12)      projection = (const float*)d_in[t];
        else if (in_sizes[t] == BATCH * 3)       origin     = (const float*)d_in[t];
    }
    float* out = (float*)d_out;

    const int blocks_per_batch = (NVOX / 4) / GRP_PER_BLK;   // 12,800
    const int grid = BATCH * blocks_per_batch;               // 51,200
    backproject_kernel<<<grid, 256>>>(origin, projection, features, voxel_size, out);
}

// round 14
// speedup vs baseline: 1.1291x; 1.1291x over previous
#include <cuda_runtime.h>
#include <cstddef>

// Problem constants (fixed by the dataset)
#define BATCH 4
#define CH    32
#define HH    120
#define WW    160
#define NXc   160
#define NYc   160
#define NZc   64
#define NVOX  (NXc * NYc * NZc)     // 1,638,400
#define HW    (HH * WW)             // 19,200

#define CH_SPLIT  8                 // threads sharing one voxel-group in pass B
#define CH_PER_T  (CH / CH_SPLIT)   // 4 channels per thread

// Per-voxel gather index, sign-encoded validity: idx >= 0 valid, -1 invalid.
// 4 * 1,638,400 * 4B = 26.2 MB -- fits in L2 (126MB) so pass B's 8x re-read
// is L2-resident after first touch.
__device__ __align__(16) int g_fidx[BATCH * NVOX];

// ---------------------------------------------------------------------------
// Pass A: one thread per voxel-group (4 z-voxels). Computes the projection
// ONCE per voxel (vs 4x redundant in R10 / 8x in R12), writes sign-encoded
// indices to scratch and the valid-mask plane directly to the output.
//
// Projection math uses explicit IEEE-rounded intrinsics to bit-match the XLA
// reference (verified rel_err == 0.0 in R6-R13):
//   world  = coords*vs + origin          (separate mul, add -- NO fma)
//   camera = sum_j P[i,j]*world[j]       (rounded products, ascending adds)
//   u      = camera_x / camera_z         (IEEE correctly-rounded divide)
//   px     = round-half-even(u)          (__float2int_rn == jnp.round)
// ---------------------------------------------------------------------------
__global__ __launch_bounds__(256) void project_kernel(
    const float* __restrict__ origin,      // [B,3]
    const float* __restrict__ projection,  // [B,3,4]
    const float* __restrict__ voxel_size,  // [1]
    float* __restrict__ out)               // for the valid plane
{
    const int groups_per_batch = NVOX / 4;             // 409,600
    int t = blockIdx.x * blockDim.x + threadIdx.x;
    if (t >= BATCH * groups_per_batch) return;

    int b  = t / groups_per_batch;
    int r  = t - b * groups_per_batch;
    int v0 = r * 4;
    int k  = v0 & (NZc - 1);
    int ij = v0 >> 6;
    int j  = ij % NYc;
    int i  = ij / NYc;

    const float vs = __ldg(voxel_size);
    const float* P = projection + b * 12;
    float P00 = __ldg(P + 0),  P01 = __ldg(P + 1),  P02 = __ldg(P + 2),  P03 = __ldg(P + 3);
    float P10 = __ldg(P + 4),  P11 = __ldg(P + 5),  P12 = __ldg(P + 6),  P13 = __ldg(P + 7);
    float P20 = __ldg(P + 8),  P21 = __ldg(P + 9),  P22 = __ldg(P + 10), P23 = __ldg(P + 11);
    float ox = __ldg(origin + b * 3 + 0);
    float oy = __ldg(origin + b * 3 + 1);
    float oz = __ldg(origin + b * 3 + 2);

    // world x/y: separately-rounded mul then add (matches coords*vs + origin)
    float wx = __fadd_rn(__fmul_rn((float)i, vs), ox);
    float wy = __fadd_rn(__fmul_rn((float)j, vs), oy);

    int   fidx[4];
    float mask[4];
#pragma unroll
    for (int m = 0; m < 4; ++m) {
        float wz = __fadd_rn(__fmul_rn((float)(k + m), vs), oz);

        float cx = __fadd_rn(__fadd_rn(__fadd_rn(__fmul_rn(P00, wx),
                                                  __fmul_rn(P01, wy)),
                                        __fmul_rn(P02, wz)), P03);
        float cy = __fadd_rn(__fadd_rn(__fadd_rn(__fmul_rn(P10, wx),
                                                  __fmul_rn(P11, wy)),
                                        __fmul_rn(P12, wz)), P13);
        float cz = __fadd_rn(__fadd_rn(__fadd_rn(__fmul_rn(P20, wx),
                                                  __fmul_rn(P21, wy)),
                                        __fmul_rn(P22, wz)), P23);

        float u  = __fdiv_rn(cx, cz);   // IEEE rn divide
        float vv = __fdiv_rn(cy, cz);
        int ipx = __float2int_rn(u);    // round-half-even == jnp.round
        int ipy = __float2int_rn(vv);
        bool ok = (ipx >= 0) && (ipy >= 0) && (ipx < WW) && (ipy < HH) && (cz > 0.0f);
        int cpx = min(max(ipx, 0), WW - 1);
        int cpy = min(max(ipy, 0), HH - 1);
        fidx[m] = ok ? (cpy * WW + cpx) : -1;   // sign-encoded validity
        mask[m] = ok ? 1.0f : 0.0f;
    }

    *reinterpret_cast<int4*>(g_fidx + (size_t)b * NVOX + v0) =
        make_int4(fidx[0], fidx[1], fidx[2], fidx[3]);

    float* vout = out + (size_t)BATCH * CH * NVOX + (size_t)b * NVOX + v0;
    __stcs(reinterpret_cast<float4*>(vout),
           make_float4(mask[0], mask[1], mask[2], mask[3]));
}

// ---------------------------------------------------------------------------
// Pass B: scatter. Thread = (voxel-group, channel-slice). Per thread:
//   1 coalesced int4 load of precomputed indices (replaces ~60 ALU + 8 IEEE
//     divides that drove R12's issue to 57%),
//   16 validity-predicated scalar gathers (native [B,C,H,W] layout -- R9
//     proved channel-transposed layout is worse),
//   4 coalesced __stcs float4 stores (streaming: keep 839MB out of L2).
// Short dependency chain (R12 geometry) with none of R12's issue pressure
// and none of R13's barrier coupling.
// ---------------------------------------------------------------------------
__global__ __launch_bounds__(256, 8) void scatter_kernel(
    const float* __restrict__ features,    // [B,C,H,W]
    float* __restrict__ out)               // volume [B,C,NVOX] ++ valid [B,NVOX]
{
    const int groups_per_batch = NVOX / 4;             // 409,600
    int gid = blockIdx.x * blockDim.x + threadIdx.x;
    if (gid >= BATCH * CH_SPLIT * groups_per_batch) return;

    int r  = gid % groups_per_batch;          // voxel group within batch
    int bh = gid / groups_per_batch;          // b * CH_SPLIT + h
    int h  = bh % CH_SPLIT;                   // channel slice
    int b  = bh / CH_SPLIT;
    int v0 = r * 4;

    int4 fi = *reinterpret_cast<const int4*>(g_fidx + (size_t)b * NVOX + v0);
    bool ok0 = fi.x >= 0, ok1 = fi.y >= 0, ok2 = fi.z >= 0, ok3 = fi.w >= 0;

    const int c0 = h * CH_PER_T;
    float* vol = out + ((size_t)b * CH + c0) * NVOX + v0;

    if (ok0 | ok1 | ok2 | ok3) {
        const float* fb = features + ((size_t)b * CH + c0) * HW;
#pragma unroll
        for (int c = 0; c < CH_PER_T; ++c) {
            const float* fc = fb + (size_t)c * HW;
            float4 o = make_float4(0.f, 0.f, 0.f, 0.f);
            // Predicated loads: invalid lanes issue NO memory request.
            if (ok0) o.x = __ldg(fc + fi.x);
            if (ok1) o.y = __ldg(fc + fi.y);
            if (ok2) o.z = __ldg(fc + fi.z);
            if (ok3) o.w = __ldg(fc + fi.w);
            __stcs(reinterpret_cast<float4*>(vol + (size_t)c * NVOX), o);
        }
    } else {
        const float4 zero = make_float4(0.f, 0.f, 0.f, 0.f);
#pragma unroll
        for (int c = 0; c < CH_PER_T; ++c)
            __stcs(reinterpret_cast<float4*>(vol + (size_t)c * NVOX), zero);
    }
}

extern "C" void kernel_launch(void* const* d_in, const int* in_sizes, int n_in,
                              void* d_out, int out_size)
{
    // Expected metadata order: origin[12], projection[48], features[2457600],
    // voxel_size[1]. Identify tensors by unique sizes as a guard.
    const float* origin     = (const float*)d_in[0];
    const float* projection = (const float*)d_in[1];
    const float* features   = (const float*)d_in[2];
    const float* voxel_size = (const float*)d_in[3];
    for (int t = 0; t < n_in; ++t) {
        if (in_sizes[t] == BATCH * CH * HH * WW) features   = (const float*)d_in[t];
        else if (in_sizes[t] == BATCH * 12)      projection = (const float*)d_in[t];
        else if (in_sizes[t] == BATCH * 3)       origin     = (const float*)d_in[t];
    }
    float* out = (float*)d_out;

    // Pass A: projections + valid plane.
    const int a_threads = BATCH * (NVOX / 4);                 // 1,638,400
    project_kernel<<<(a_threads + 255) / 256, 256>>>(origin, projection,
                                                     voxel_size, out);

    // Pass B: gather + scatter of the feature volume.
    const int b_threads = BATCH * CH_SPLIT * (NVOX / 4);      // 13,107,200
    scatter_kernel<<<(b_threads + 255) / 256, 256>>>(features, out);
}

// round 15
// speedup vs baseline: 1.2098x; 1.0715x over previous
#include <cuda_runtime.h>
#include <cstddef>

// Problem constants (fixed by the dataset)
#define BATCH 4
#define CH    32
#define HH    120
#define WW    160
#define NXc   160
#define NYc   160
#define NZc   64
#define NVOX  (NXc * NYc * NZc)     // 1,638,400
#define HW    (HH * WW)             // 19,200

#define CH_SPLIT  8                 // threads sharing one voxel-group in pass B
#define CH_PER_T  (CH / CH_SPLIT)   // 4 channels per thread

#define TP_THREADS (BATCH * HW)     // 76,800 transpose threads
#define TP_BLOCKS  (TP_THREADS / 256)          // 300
#define PR_THREADS (BATCH * (NVOX / 4))        // 1,638,400 projection threads
#define PR_BLOCKS  (PR_THREADS / 256)          // 6400

// Channel-transposed features [B][HW][C]: one pixel's 32 channels = exactly
// one 128B cache line -> a single LDG.128 fetches 4 channels (4 outputs per
// gather wavefront instead of 1 with scalar gathers from [C][HW]).
__device__ __align__(128) float g_tfeat[BATCH * HW * CH];

// Per-voxel gather index as int16 (HW=19200 < 32768), -1 = invalid.
// 13.1 MB -- L2-resident for pass B's re-reads.
__device__ __align__(16) short g_sidx[BATCH * NVOX];

// ---------------------------------------------------------------------------
// Pass A (merged): blocks [0,300) transpose features to [HW][C]; blocks
// [300, 6700) project one voxel-group each (projection computed ONCE per
// voxel), writing short4 scratch + the valid-mask plane.
//
// Projection math uses explicit IEEE-rounded intrinsics to bit-match the XLA
// reference (verified rel_err == 0.0 in R6-R14):
//   world  = coords*vs + origin          (separate mul, add -- NO fma)
//   camera = sum_j P[i,j]*world[j]       (rounded products, ascending adds)
//   u      = camera_x / camera_z         (IEEE correctly-rounded divide)
//   px     = round-half-even(u)          (__float2int_rn == jnp.round)
// ---------------------------------------------------------------------------
__global__ __launch_bounds__(256) void prepare_kernel(
    const float* __restrict__ origin,      // [B,3]
    const float* __restrict__ projection,  // [B,3,4]
    const float* __restrict__ features,    // [B,C,H,W]
    const float* __restrict__ voxel_size,  // [1]
    float* __restrict__ out)               // for the valid plane
{
    if (blockIdx.x < TP_BLOCKS) {
        // ---- transpose: [B,C,H,W] -> [B,HW,C] ----
        int t = blockIdx.x * 256 + threadIdx.x;   // < 76,800
        int b = t / HW;
        int p = t - b * HW;
        const float* src = features + (size_t)b * CH * HW + p;
        float* dst = g_tfeat + (size_t)t * CH;
#pragma unroll
        for (int c4 = 0; c4 < CH; c4 += 4) {
            float4 o;
            o.x = __ldg(src + (size_t)(c4 + 0) * HW);
            o.y = __ldg(src + (size_t)(c4 + 1) * HW);
            o.z = __ldg(src + (size_t)(c4 + 2) * HW);
            o.w = __ldg(src + (size_t)(c4 + 3) * HW);
            *reinterpret_cast<float4*>(dst + c4) = o;
        }
        return;
    }

    // ---- projection: one thread per voxel-group ----
    const int groups_per_batch = NVOX / 4;             // 409,600
    int t = (blockIdx.x - TP_BLOCKS) * 256 + threadIdx.x;  // < 1,638,400

    int b  = t / groups_per_batch;
    int r  = t - b * groups_per_batch;
    int v0 = r * 4;
    int k  = v0 & (NZc - 1);
    int ij = v0 >> 6;
    int j  = ij % NYc;
    int i  = ij / NYc;

    const float vs = __ldg(voxel_size);
    const float* P = projection + b * 12;
    float P00 = __ldg(P + 0),  P01 = __ldg(P + 1),  P02 = __ldg(P + 2),  P03 = __ldg(P + 3);
    float P10 = __ldg(P + 4),  P11 = __ldg(P + 5),  P12 = __ldg(P + 6),  P13 = __ldg(P + 7);
    float P20 = __ldg(P + 8),  P21 = __ldg(P + 9),  P22 = __ldg(P + 10), P23 = __ldg(P + 11);
    float ox = __ldg(origin + b * 3 + 0);
    float oy = __ldg(origin + b * 3 + 1);
    float oz = __ldg(origin + b * 3 + 2);

    // world x/y: separately-rounded mul then add (matches coords*vs + origin)
    float wx = __fadd_rn(__fmul_rn((float)i, vs), ox);
    float wy = __fadd_rn(__fmul_rn((float)j, vs), oy);

    short fidx[4];
    float mask[4];
#pragma unroll
    for (int m = 0; m < 4; ++m) {
        float wz = __fadd_rn(__fmul_rn((float)(k + m), vs), oz);

        float cx = __fadd_rn(__fadd_rn(__fadd_rn(__fmul_rn(P00, wx),
                                                  __fmul_rn(P01, wy)),
                                        __fmul_rn(P02, wz)), P03);
        float cy = __fadd_rn(__fadd_rn(__fadd_rn(__fmul_rn(P10, wx),
                                                  __fmul_rn(P11, wy)),
                                        __fmul_rn(P12, wz)), P13);
        float cz = __fadd_rn(__fadd_rn(__fadd_rn(__fmul_rn(P20, wx),
                                                  __fmul_rn(P21, wy)),
                                        __fmul_rn(P22, wz)), P23);

        float u  = __fdiv_rn(cx, cz);   // IEEE rn divide
        float vv = __fdiv_rn(cy, cz);
        int ipx = __float2int_rn(u);    // round-half-even == jnp.round
        int ipy = __float2int_rn(vv);
        bool ok = (ipx >= 0) && (ipy >= 0) && (ipx < WW) && (ipy < HH) && (cz > 0.0f);
        int cpx = min(max(ipx, 0), WW - 1);
        int cpy = min(max(ipy, 0), HH - 1);
        fidx[m] = ok ? (short)(cpy * WW + cpx) : (short)-1;
        mask[m] = ok ? 1.0f : 0.0f;
    }

    *reinterpret_cast<short4*>(g_sidx + (size_t)b * NVOX + v0) =
        make_short4(fidx[0], fidx[1], fidx[2], fidx[3]);

    float* vout = out + (size_t)BATCH * CH * NVOX + (size_t)b * NVOX + v0;
    __stcs(reinterpret_cast<float4*>(vout),
           make_float4(mask[0], mask[1], mask[2], mask[3]));
}

// ---------------------------------------------------------------------------
// Pass B: scatter. Thread = (voxel-group, channel-slice of 4). Per thread:
//   1 coalesced short4 load of precomputed indices,
//   4 validity-predicated LDG.128 gathers from the channel-contiguous
//     [HW][C] features -- 4 channels per wavefront instead of 1 (the scalar
//     gathers in R14 generated ~40M wavefronts vs 6.5M store wavefronts and
//     made the kernel L1tex-bound; this cuts gathers to ~13.5M),
//   4x4 register transpose,
//   4 coalesced __stcs float4 stores (streaming).
// ---------------------------------------------------------------------------
__global__ __launch_bounds__(256, 8) void scatter_kernel(
    float* __restrict__ out)               // volume [B,C,NVOX] ++ valid [B,NVOX]
{
    const int groups_per_batch = NVOX / 4;             // 409,600
    int gid = blockIdx.x * blockDim.x + threadIdx.x;
    if (gid >= BATCH * CH_SPLIT * groups_per_batch) return;

    int r  = gid % groups_per_batch;          // voxel group within batch
    int bh = gid / groups_per_batch;          // b * CH_SPLIT + h
    int h  = bh % CH_SPLIT;                   // channel slice
    int b  = bh / CH_SPLIT;
    int v0 = r * 4;

    short4 fs = *reinterpret_cast<const short4*>(g_sidx + (size_t)b * NVOX + v0);
    bool ok0 = fs.x >= 0, ok1 = fs.y >= 0, ok2 = fs.z >= 0, ok3 = fs.w >= 0;

    const int c0 = h * CH_PER_T;
    float* vol = out + ((size_t)b * CH + c0) * NVOX + v0;

    if (ok0 | ok1 | ok2 | ok3) {
        const float* tf = g_tfeat + (size_t)b * HW * CH + c0;
        const float4 zero4 = make_float4(0.f, 0.f, 0.f, 0.f);
        // 4 channels of each voxel in ONE vector load (16B of the pixel's
        // 128B channel line).
        float4 a0 = ok0 ? *reinterpret_cast<const float4*>(tf + (int)fs.x * CH) : zero4;
        float4 a1 = ok1 ? *reinterpret_cast<const float4*>(tf + (int)fs.y * CH) : zero4;
        float4 a2 = ok2 ? *reinterpret_cast<const float4*>(tf + (int)fs.z * CH) : zero4;
        float4 a3 = ok3 ? *reinterpret_cast<const float4*>(tf + (int)fs.w * CH) : zero4;
        // 4x4 register transpose -> per-channel voxel vectors.
        __stcs(reinterpret_cast<float4*>(vol + (size_t)0 * NVOX),
               make_float4(a0.x, a1.x, a2.x, a3.x));
        __stcs(reinterpret_cast<float4*>(vol + (size_t)1 * NVOX),
               make_float4(a0.y, a1.y, a2.y, a3.y));
        __stcs(reinterpret_cast<float4*>(vol + (size_t)2 * NVOX),
               make_float4(a0.z, a1.z, a2.z, a3.z));
        __stcs(reinterpret_cast<float4*>(vol + (size_t)3 * NVOX),
               make_float4(a0.w, a1.w, a2.w, a3.w));
    } else {
        const float4 zero = make_float4(0.f, 0.f, 0.f, 0.f);
#pragma unroll
        for (int c = 0; c < CH_PER_T; ++c)
            __stcs(reinterpret_cast<float4*>(vol + (size_t)c * NVOX), zero);
    }
}

extern "C" void kernel_launch(void* const* d_in, const int* in_sizes, int n_in,
                              void* d_out, int out_size)
{
    // Expected metadata order: origin[12], projection[48], features[2457600],
    // voxel_size[1]. Identify tensors by unique sizes as a guard.
    const float* origin     = (const float*)d_in[0];
    const float* projection = (const float*)d_in[1];
    const float* features   = (const float*)d_in[2];
    const float* voxel_size = (const float*)d_in[3];
    for (int t = 0; t < n_in; ++t) {
        if (in_sizes[t] == BATCH * CH * HH * WW) features   = (const float*)d_in[t];
        else if (in_sizes[t] == BATCH * 12)      projection = (const float*)d_in[t];
        else if (in_sizes[t] == BATCH * 3)       origin     = (const float*)d_in[t];
    }
    float* out = (float*)d_out;

    // Pass A: feature transpose + projections + valid plane (merged grid).
    prepare_kernel<<<TP_BLOCKS + PR_BLOCKS, 256>>>(origin, projection,
                                                   features, voxel_size, out);

    // Pass B: vector-gather + scatter of the feature volume.
    const int b_threads = BATCH * CH_SPLIT * (NVOX / 4);      // 13,107,200
    scatter_kernel<<<(b_threads + 255) / 256, 256>>>(out);
}